// round 13
// baseline (speedup 1.0000x reference)
#include <cuda_runtime.h>
#include <cuda_bf16.h>
#include <cuda_fp16.h>
#include <cstdint>

#define NODES_MAX 100000
#define E_MAX     1600000

// ---------------- device scratch (static, allocation-free) ----------------
__device__ __half g_H16[(size_t)NODES_MAX * 128];        // messages (fp16)
__device__ __nv_bfloat16 g_Xhi[(size_t)NODES_MAX * 128]; // X_eff hi (bf16)
__device__ __nv_bfloat16 g_Xlo[(size_t)NODES_MAX * 128]; // X_eff lo (bf16)
__device__ float  g_out_norm[NODES_MAX];
__device__ float  g_in_norm[NODES_MAX];
__device__ int    g_odeg[NODES_MAX];
__device__ int    g_ideg[NODES_MAX];
__device__ int    g_row_beg[NODES_MAX];
__device__ int    g_fill[NODES_MAX];
__device__ int    g_csr_src[E_MAX];
__device__ int    g_alloc_ctr;
__device__ __nv_bfloat16 g_W1hi[128 * 128], g_W1lo[128 * 128];   // W^T splits [n][k]
__device__ __nv_bfloat16 g_W2hi[128 * 128], g_W2lo[128 * 128];
__device__ __nv_bfloat16 g_W3hi[64 * 128],  g_W3lo[64 * 128];

__device__ __forceinline__ uint32_t smem_u32(const void* p) {
    uint32_t a;
    asm("{ .reg .u64 t; cvta.to.shared.u64 t, %1; cvt.u32.u64 %0, t; }" : "=r"(a) : "l"(p));
    return a;
}

#define LDSM_X4(r0, r1, r2, r3, addr) \
    asm volatile("ldmatrix.sync.aligned.m8n8.x4.shared.b16 {%0,%1,%2,%3}, [%4];" \
        : "=r"(r0), "=r"(r1), "=r"(r2), "=r"(r3) : "r"(addr))

#define MMA_BF16(c, a0, a1, a2, a3, b0, b1) \
    asm volatile("mma.sync.aligned.m16n8k16.row.col.f32.bf16.bf16.f32 " \
        "{%0,%1,%2,%3}, {%4,%5,%6,%7}, {%8,%9}, {%0,%1,%2,%3};" \
        : "+f"((c)[0]), "+f"((c)[1]), "+f"((c)[2]), "+f"((c)[3]) \
        : "r"(a0), "r"(a1), "r"(a2), "r"(a3), "r"(b0), "r"(b1))

// unpack uint2 (4 fp16) and accumulate into float4
__device__ __forceinline__ void acc_h4(float4& acc, uint2 u) {
    __half2 h0 = *(__half2*)&u.x;
    __half2 h1 = *(__half2*)&u.y;
    float2 f0 = __half22float2(h0);
    float2 f1 = __half22float2(h1);
    acc.x += f0.x; acc.y += f0.y; acc.z += f1.x; acc.w += f1.y;
}

// bf16 hi/lo split of two floats -> packed bf16x2 words
__device__ __forceinline__ void split2(float a, float b, uint32_t& hi, uint32_t& lo) {
    __nv_bfloat16 h0 = __float2bfloat16(a);
    __nv_bfloat16 h1 = __float2bfloat16(b);
    __nv_bfloat16 l0 = __float2bfloat16(a - __bfloat162float(h0));
    __nv_bfloat16 l1 = __float2bfloat16(b - __bfloat162float(h1));
    __nv_bfloat162 ph = __nv_bfloat162(h0, h1);
    __nv_bfloat162 pl = __nv_bfloat162(l0, l1);
    hi = *(uint32_t*)&ph;
    lo = *(uint32_t*)&pl;
}

// ---------------- degree ----------------
__global__ void k_init_deg(int n) {
    int i = blockIdx.x * blockDim.x + threadIdx.x;
    if (i < n) { g_odeg[i] = 1; g_ideg[i] = 1; }
    if (i == 0) g_alloc_ctr = 0;
}
__global__ void k_count_deg(const int* __restrict__ src, const int* __restrict__ dst, int E) {
    int i = blockIdx.x * blockDim.x + threadIdx.x;
    int st = gridDim.x * blockDim.x;
    for (; i < E; i += st) {
        atomicAdd(&g_odeg[src[i]], 1);
        atomicAdd(&g_ideg[dst[i]], 1);
    }
}

// ---------------- CSR segment allocation + norms (fused) ----------------
__global__ void __launch_bounds__(256)
k_alloc(int n) {
    __shared__ int warp_sums[8];
    __shared__ int block_base;
    int i    = blockIdx.x * 256 + threadIdx.x;
    int lane = threadIdx.x & 31;
    int wid  = threadIdx.x >> 5;
    int ideg = (i < n) ? g_ideg[i] : 1;
    int deg  = ideg - 1;
    if (i < n) {
        g_out_norm[i] = rsqrtf((float)g_odeg[i]);
        g_in_norm[i]  = rsqrtf((float)ideg);
    }
    int v = deg;
#pragma unroll
    for (int off = 1; off < 32; off <<= 1) {
        int t = __shfl_up_sync(0xffffffffu, v, off);
        if (lane >= off) v += t;
    }
    if (lane == 31) warp_sums[wid] = v;
    __syncthreads();
    if (wid == 0) {
        int s = (lane < 8) ? warp_sums[lane] : 0;
#pragma unroll
        for (int off = 1; off < 8; off <<= 1) {
            int t = __shfl_up_sync(0xffffffffu, s, off);
            if (lane >= off) s += t;
        }
        if (lane < 8) warp_sums[lane] = s;
        if (lane == 7) block_base = atomicAdd(&g_alloc_ctr, s);
    }
    __syncthreads();
    int base = block_base + ((wid > 0) ? warp_sums[wid - 1] : 0) + (v - deg);
    if (i < n) { g_row_beg[i] = base; g_fill[i] = base; }
}

__global__ void k_scatter(const int* __restrict__ src, const int* __restrict__ dst, int E) {
    int i = blockIdx.x * blockDim.x + threadIdx.x;
    int st = gridDim.x * blockDim.x;
    for (; i < E; i += st) {
        int d = dst[i];
        int pos = atomicAdd(&g_fill[d], 1);
        g_csr_src[pos] = src[i];
    }
}

// ---------------- W prep: transpose + bf16 hi/lo split, all 3 layers ----------------
__global__ void k_prepW_all(const float* __restrict__ W1, const float* __restrict__ W2,
                            const float* __restrict__ W3) {
    int i = blockIdx.x * blockDim.x + threadIdx.x;   // 0 .. 40959
    const float* W; __nv_bfloat16 *Hi, *Lo; int dout, idx;
    if (i < 16384)      { W = W1; Hi = g_W1hi; Lo = g_W1lo; dout = 128; idx = i; }
    else if (i < 32768) { W = W2; Hi = g_W2hi; Lo = g_W2lo; dout = 128; idx = i - 16384; }
    else if (i < 40960) { W = W3; Hi = g_W3hi; Lo = g_W3lo; dout = 64;  idx = i - 32768; }
    else return;
    int nn = idx % dout;
    int k  = idx / dout;
    float w = W[k * dout + nn];
    __nv_bfloat16 hi = __float2bfloat16(w);
    float rlo = w - __bfloat162float(hi);
    Hi[nn * 128 + k] = hi;
    Lo[nn * 128 + k] = __float2bfloat16(rlo);
}

// ---------------- layer-1 X prep: X1 = feat * out_norm, split hi/lo ----------------
__global__ void k_prepX1(const float* __restrict__ feat, int n) {
    int i = blockIdx.x * blockDim.x + threadIdx.x;   // over n*32 float4s
    if (i >= n * 32) return;
    int row = i >> 5;
    float on = g_out_norm[row];
    float4 v = ((const float4*)feat)[i];
    v.x *= on; v.y *= on; v.z *= on; v.w *= on;
    uint32_t h01, l01, h23, l23;
    split2(v.x, v.y, h01, l01);
    split2(v.z, v.w, h23, l23);
    ((uint2*)g_Xhi)[i] = make_uint2(h01, h23);
    ((uint2*)g_Xlo)[i] = make_uint2(l01, l23);
}

// ---------------- bf16-split HMMA GEMM (lean staging: pure copies) ----------------
// 128-row tiles, 512 threads (16 warps: 8 row-groups x 2 col-halves).
// A comes pre-split from g_Xhi/g_Xlo; output H16 fp16 messages.
template <int DOUT, int LAYER>
__global__ void __launch_bounds__(512)
k_gemm_mma(int n)
{
    constexpr int NTW   = DOUT / 16;       // n-tiles per warp
    constexpr int ASTB  = 272;             // row stride bytes (136 bf16)
    constexpr int SM_AHI = 0;
    constexpr int SM_ALO = SM_AHI + 128 * ASTB;
    constexpr int SM_BHI = SM_ALO + 128 * ASTB;
    constexpr int SM_BLO = SM_BHI + DOUT * ASTB;

    const __nv_bfloat16* WHi = (LAYER == 1) ? g_W1hi : (LAYER == 2) ? g_W2hi : g_W3hi;
    const __nv_bfloat16* WLo = (LAYER == 1) ? g_W1lo : (LAYER == 2) ? g_W2lo : g_W3lo;

    extern __shared__ char sm[];
    const uint32_t smb = smem_u32(sm);
    const int t    = threadIdx.x;
    const int lane = t & 31;
    const int wid  = t >> 5;
    const int row0 = blockIdx.x * 128;

    // ---- stage B (W^T hi/lo, pure copy) ----
    for (int g = t; g < DOUT * 16; g += 512) {
        int nn = g >> 4, kg = g & 15;
        char* dhi = sm + SM_BHI + nn * ASTB + kg * 16;
        char* dlo = sm + SM_BLO + nn * ASTB + kg * 16;
        *(uint4*)dhi = *(const uint4*)((const char*)WHi + (size_t)g * 16);
        *(uint4*)dlo = *(const uint4*)((const char*)WLo + (size_t)g * 16);
    }

    // ---- stage A (pure copy from pre-split X) ----
    const uint4* Xh4 = (const uint4*)g_Xhi;   // 16 uint4 per 128-wide row
    const uint4* Xl4 = (const uint4*)g_Xlo;
    for (int g = t; g < 128 * 16; g += 512) {
        int r = g >> 4, kg = g & 15;
        int row = row0 + r;
        uint4 vh = make_uint4(0u, 0u, 0u, 0u);
        uint4 vl = make_uint4(0u, 0u, 0u, 0u);
        if (row < n) {
            vh = Xh4[(size_t)row * 16 + kg];
            vl = Xl4[(size_t)row * 16 + kg];
        }
        *(uint4*)(sm + SM_AHI + r * ASTB + kg * 16) = vh;
        *(uint4*)(sm + SM_ALO + r * ASTB + kg * 16) = vl;
    }
    __syncthreads();

    // ---- compute ----
    const int m0 = (wid >> 1) * 16;
    const int ch = wid & 1;
    const int qd = lane >> 3;
    const int ri = lane & 7;

    float acc[NTW][4];
#pragma unroll
    for (int nt = 0; nt < NTW; nt++) { acc[nt][0] = acc[nt][1] = acc[nt][2] = acc[nt][3] = 0.f; }

    const uint32_t a_off[3] = { smb + SM_AHI, smb + SM_ALO, smb + SM_AHI };
    const uint32_t b_off[3] = { smb + SM_BHI, smb + SM_BHI, smb + SM_BLO };

#pragma unroll
    for (int term = 0; term < 3; term++) {
        uint32_t aAddr = a_off[term] + (uint32_t)(m0 + ri + ((qd & 1) << 3)) * ASTB
                       + (uint32_t)((qd & 2) ? 16 : 0);
        uint32_t bBase = b_off[term] + (uint32_t)(ri + ((qd & 1) << 3)) * ASTB
                       + (uint32_t)((qd & 2) ? 16 : 0);
#pragma unroll
        for (int kk = 0; kk < 8; kk++) {
            uint32_t a0, a1, a2, a3;
            LDSM_X4(a0, a1, a2, a3, aAddr + kk * 32);
#pragma unroll
            for (int p = 0; p < NTW / 2; p++) {
                uint32_t bAddr = bBase + (uint32_t)((ch * NTW + 2 * p) * 8) * ASTB + kk * 32;
                uint32_t b0, b1, b2, b3;
                LDSM_X4(b0, b1, b2, b3, bAddr);
                MMA_BF16(acc[2 * p],     a0, a1, a2, a3, b0, b2);
                MMA_BF16(acc[2 * p + 1], a0, a1, a2, a3, b1, b3);
            }
        }
    }

    // ---- epilogue: fp16 message writes ----
    const int frow = row0 + m0 + (lane >> 2);
    const int fcol = (lane & 3) * 2;
    uint32_t* H32 = (uint32_t*)g_H16;
#pragma unroll
    for (int nt = 0; nt < NTW; nt++) {
        int col = (ch * NTW + nt) * 8 + fcol;
        if (frow < n) {
            __half2 h = __floats2half2_rn(acc[nt][0], acc[nt][1]);
            H32[((size_t)frow * DOUT + col) >> 1] = *(uint32_t*)&h;
        }
        if (frow + 8 < n) {
            __half2 h = __floats2half2_rn(acc[nt][2], acc[nt][3]);
            H32[((size_t)(frow + 8) * DOUT + col) >> 1] = *(uint32_t*)&h;
        }
    }
}

// ---------------- fused aggregation + next-layer epilogue ----------------
// Gathers fp16 messages, fp32 accumulate (self-loop init), then
// X_next = relu(acc*in_norm + b)*out_norm split to bf16 hi/lo.
__global__ void __launch_bounds__(256)
k_agg128_fuse(const float* __restrict__ bprev, int n) {
    int w    = (blockIdx.x * blockDim.x + threadIdx.x) >> 5;
    int lane = threadIdx.x & 31;
    if (w >= n) return;
    const uint2* H2 = (const uint2*)g_H16;    // row = 32 uint2 (128 fp16)
    int beg = g_row_beg[w];
    int end = beg + g_ideg[w] - 1;
    float4 acc = make_float4(0.f, 0.f, 0.f, 0.f);
    acc_h4(acc, H2[(size_t)w * 32 + lane]);   // self-loop
    int j = beg;
    for (; j + 1 < end; j += 2) {
        int s0 = __ldg(&g_csr_src[j]);
        int s1 = __ldg(&g_csr_src[j + 1]);
        uint2 u0 = H2[(size_t)s0 * 32 + lane];
        uint2 u1 = H2[(size_t)s1 * 32 + lane];
        acc_h4(acc, u0);
        acc_h4(acc, u1);
    }
    if (j < end) {
        acc_h4(acc, H2[(size_t)__ldg(&g_csr_src[j]) * 32 + lane]);
    }
    float inn = g_in_norm[w];
    float on  = g_out_norm[w];
    float4 bb = ((const float4*)bprev)[lane];
    float x0 = fmaxf(fmaf(acc.x, inn, bb.x), 0.f) * on;
    float x1 = fmaxf(fmaf(acc.y, inn, bb.y), 0.f) * on;
    float x2 = fmaxf(fmaf(acc.z, inn, bb.z), 0.f) * on;
    float x3 = fmaxf(fmaf(acc.w, inn, bb.w), 0.f) * on;
    uint32_t h01, l01, h23, l23;
    split2(x0, x1, h01, l01);
    split2(x2, x3, h23, l23);
    ((uint2*)g_Xhi)[(size_t)w * 32 + lane] = make_uint2(h01, h23);
    ((uint2*)g_Xlo)[(size_t)w * 32 + lane] = make_uint2(l01, l23);
}

// 64-wide, final layer: half-warp per dst node; out = acc*in_norm + b3.
__global__ void __launch_bounds__(256)
k_agg64_final(const float* __restrict__ b3, float* __restrict__ out, int n) {
    int gt   = blockIdx.x * blockDim.x + threadIdx.x;
    int lane = gt & 31;
    int w    = gt >> 5;
    int sub  = lane >> 4;
    int l16  = lane & 15;
    int node = w * 2 + sub;
    if (node >= n) return;
    const uint2* H2 = (const uint2*)g_H16;    // row = 16 uint2 (64 fp16)
    int beg = g_row_beg[node];
    int end = beg + g_ideg[node] - 1;
    float4 acc = make_float4(0.f, 0.f, 0.f, 0.f);
    acc_h4(acc, H2[(size_t)node * 16 + l16]); // self-loop
    int j = beg;
    for (; j + 1 < end; j += 2) {
        int s0 = __ldg(&g_csr_src[j]);
        int s1 = __ldg(&g_csr_src[j + 1]);
        uint2 u0 = H2[(size_t)s0 * 16 + l16];
        uint2 u1 = H2[(size_t)s1 * 16 + l16];
        acc_h4(acc, u0);
        acc_h4(acc, u1);
    }
    if (j < end) {
        acc_h4(acc, H2[(size_t)__ldg(&g_csr_src[j]) * 16 + l16]);
    }
    float inn = g_in_norm[node];
    float4 bb = ((const float4*)b3)[l16];
    float4 o;
    o.x = fmaf(acc.x, inn, bb.x);
    o.y = fmaf(acc.y, inn, bb.y);
    o.z = fmaf(acc.z, inn, bb.z);
    o.w = fmaf(acc.w, inn, bb.w);
    ((float4*)out)[(size_t)node * 16 + l16] = o;
}

// ---------------- launcher ----------------
extern "C" void kernel_launch(void* const* d_in, const int* in_sizes, int n_in,
                              void* d_out, int out_size)
{
    const float* feat = (const float*)d_in[0];
    const int*   src  = (const int*)d_in[1];
    const int*   dst  = (const int*)d_in[2];
    const float* W1   = (const float*)d_in[3];
    const float* b1   = (const float*)d_in[4];
    const float* W2   = (const float*)d_in[5];
    const float* b2   = (const float*)d_in[6];
    const float* W3   = (const float*)d_in[7];
    const float* b3   = (const float*)d_in[8];
    float*       out  = (float*)d_out;

    const int n = in_sizes[0] / 128;   // 100000
    const int E = in_sizes[1];         // 1600000

    const int smem128 = (128 + 128 + 128 + 128) * 272;   // 139,264 B
    const int smem64  = (128 + 128 + 64 + 64) * 272;     // 104,448 B
    cudaFuncSetAttribute((const void*)k_gemm_mma<128, 1>,
                         cudaFuncAttributeMaxDynamicSharedMemorySize, smem128);
    cudaFuncSetAttribute((const void*)k_gemm_mma<128, 2>,
                         cudaFuncAttributeMaxDynamicSharedMemorySize, smem128);
    cudaFuncSetAttribute((const void*)k_gemm_mma<64, 3>,
                         cudaFuncAttributeMaxDynamicSharedMemorySize, smem64);

    // W prep for all layers (once, up front)
    k_prepW_all<<<(40960 + 255) / 256, 256>>>(W1, W2, W3);

    // degrees
    k_init_deg<<<(n + 255) / 256, 256>>>(n);
    k_count_deg<<<1024, 256>>>(src, dst, E);

    // CSR build + norms (fused)
    k_alloc<<<(n + 255) / 256, 256>>>(n);
    k_scatter<<<1024, 256>>>(src, dst, E);

    // layer-1 input prep (feat * out_norm, hi/lo split)
    k_prepX1<<<(n * 32 + 255) / 256, 256>>>(feat, n);

    const int gblocks = (n + 127) / 128;   // 782

    // layer 1
    k_gemm_mma<128, 1><<<gblocks, 512, smem128>>>(n);
    k_agg128_fuse<<<(n * 32 + 255) / 256, 256>>>(b1, n);

    // layer 2
    k_gemm_mma<128, 2><<<gblocks, 512, smem128>>>(n);
    k_agg128_fuse<<<(n * 32 + 255) / 256, 256>>>(b2, n);

    // layer 3 (64-wide)
    k_gemm_mma<64, 3><<<gblocks, 512, smem64>>>(n);
    k_agg64_final<<<(n * 16 + 255) / 256, 256>>>(b3, out, n);
}

// round 14
// speedup vs baseline: 1.4801x; 1.4801x over previous
#include <cuda_runtime.h>
#include <cuda_fp16.h>
#include <cstdint>

#define NODES_MAX 100000
#define E_MAX     1600000

// ---------------- device scratch (static, allocation-free) ----------------
__device__ __half g_H16[(size_t)NODES_MAX * 128];   // messages (fp16)
__device__ __half g_X16[(size_t)NODES_MAX * 128];   // X_eff (fp16)
__device__ float  g_out_norm[NODES_MAX];
__device__ float  g_in_norm[NODES_MAX];
__device__ int    g_odeg[NODES_MAX];
__device__ int    g_ideg[NODES_MAX];
__device__ int    g_row_beg[NODES_MAX];
__device__ int    g_fill[NODES_MAX];
__device__ int    g_csr_src[E_MAX];
__device__ int    g_alloc_ctr;
__device__ __half g_W1h[128 * 128];                 // W^T fp16 [n][k]
__device__ __half g_W2h[128 * 128];
__device__ __half g_W3h[64 * 128];

__device__ __forceinline__ uint32_t smem_u32(const void* p) {
    uint32_t a;
    asm("{ .reg .u64 t; cvta.to.shared.u64 t, %1; cvt.u32.u64 %0, t; }" : "=r"(a) : "l"(p));
    return a;
}

#define LDSM_X4(r0, r1, r2, r3, addr) \
    asm volatile("ldmatrix.sync.aligned.m8n8.x4.shared.b16 {%0,%1,%2,%3}, [%4];" \
        : "=r"(r0), "=r"(r1), "=r"(r2), "=r"(r3) : "r"(addr))

#define MMA_F16(c, a0, a1, a2, a3, b0, b1) \
    asm volatile("mma.sync.aligned.m16n8k16.row.col.f32.f16.f16.f32 " \
        "{%0,%1,%2,%3}, {%4,%5,%6,%7}, {%8,%9}, {%0,%1,%2,%3};" \
        : "+f"((c)[0]), "+f"((c)[1]), "+f"((c)[2]), "+f"((c)[3]) \
        : "r"(a0), "r"(a1), "r"(a2), "r"(a3), "r"(b0), "r"(b1))

// unpack uint2 (4 fp16) and accumulate into float4
__device__ __forceinline__ void acc_h4(float4& acc, uint2 u) {
    __half2 h0 = *(__half2*)&u.x;
    __half2 h1 = *(__half2*)&u.y;
    float2 f0 = __half22float2(h0);
    float2 f1 = __half22float2(h1);
    acc.x += f0.x; acc.y += f0.y; acc.z += f1.x; acc.w += f1.y;
}

// ---------------- degree ----------------
__global__ void k_init_deg(int n) {
    int i = blockIdx.x * blockDim.x + threadIdx.x;
    if (i < n) { g_odeg[i] = 1; g_ideg[i] = 1; }
    if (i == 0) g_alloc_ctr = 0;
}
__global__ void k_count_deg(const int* __restrict__ src, const int* __restrict__ dst, int E) {
    int i = blockIdx.x * blockDim.x + threadIdx.x;
    int st = gridDim.x * blockDim.x;
    for (; i < E; i += st) {
        atomicAdd(&g_odeg[src[i]], 1);
        atomicAdd(&g_ideg[dst[i]], 1);
    }
}

// ---------------- CSR segment allocation + norms (fused) ----------------
__global__ void __launch_bounds__(256)
k_alloc(int n) {
    __shared__ int warp_sums[8];
    __shared__ int block_base;
    int i    = blockIdx.x * 256 + threadIdx.x;
    int lane = threadIdx.x & 31;
    int wid  = threadIdx.x >> 5;
    int ideg = (i < n) ? g_ideg[i] : 1;
    int deg  = ideg - 1;
    if (i < n) {
        g_out_norm[i] = rsqrtf((float)g_odeg[i]);
        g_in_norm[i]  = rsqrtf((float)ideg);
    }
    int v = deg;
#pragma unroll
    for (int off = 1; off < 32; off <<= 1) {
        int t = __shfl_up_sync(0xffffffffu, v, off);
        if (lane >= off) v += t;
    }
    if (lane == 31) warp_sums[wid] = v;
    __syncthreads();
    if (wid == 0) {
        int s = (lane < 8) ? warp_sums[lane] : 0;
#pragma unroll
        for (int off = 1; off < 8; off <<= 1) {
            int t = __shfl_up_sync(0xffffffffu, s, off);
            if (lane >= off) s += t;
        }
        if (lane < 8) warp_sums[lane] = s;
        if (lane == 7) block_base = atomicAdd(&g_alloc_ctr, s);
    }
    __syncthreads();
    int base = block_base + ((wid > 0) ? warp_sums[wid - 1] : 0) + (v - deg);
    if (i < n) { g_row_beg[i] = base; g_fill[i] = base; }
}

__global__ void k_scatter(const int* __restrict__ src, const int* __restrict__ dst, int E) {
    int i = blockIdx.x * blockDim.x + threadIdx.x;
    int st = gridDim.x * blockDim.x;
    for (; i < E; i += st) {
        int d = dst[i];
        int pos = atomicAdd(&g_fill[d], 1);
        g_csr_src[pos] = src[i];
    }
}

// ---------------- W prep: transpose to fp16, all 3 layers ----------------
__global__ void k_prepW_all(const float* __restrict__ W1, const float* __restrict__ W2,
                            const float* __restrict__ W3) {
    int i = blockIdx.x * blockDim.x + threadIdx.x;   // 0 .. 40959
    const float* W; __half* Wh; int dout, idx;
    if (i < 16384)      { W = W1; Wh = g_W1h; dout = 128; idx = i; }
    else if (i < 32768) { W = W2; Wh = g_W2h; dout = 128; idx = i - 16384; }
    else if (i < 40960) { W = W3; Wh = g_W3h; dout = 64;  idx = i - 32768; }
    else return;
    int nn = idx % dout;
    int k  = idx / dout;
    Wh[nn * 128 + k] = __float2half_rn(W[k * dout + nn]);
}

// ---------------- layer-1 X prep: X1 = feat * out_norm (fp16) ----------------
__global__ void k_prepX1(const float* __restrict__ feat, int n) {
    int i = blockIdx.x * blockDim.x + threadIdx.x;   // over n*32 float4s
    if (i >= n * 32) return;
    int row = i >> 5;
    float on = g_out_norm[row];
    float4 v = ((const float4*)feat)[i];
    __half2 h0 = __floats2half2_rn(v.x * on, v.y * on);
    __half2 h1 = __floats2half2_rn(v.z * on, v.w * on);
    ((uint2*)g_X16)[i] = make_uint2(*(uint32_t*)&h0, *(uint32_t*)&h1);
}

// ---------------- fp16 HMMA GEMM (single term, fp32 accum) ----------------
// 128-row tiles, 512 threads (16 warps: 8 row-groups x 2 col-halves).
// A = g_X16 (fp16), B = W^T fp16; output fp16 messages to g_H16.
template <int DOUT, int LAYER>
__global__ void __launch_bounds__(512, 2)
k_gemm_mma(int n)
{
    constexpr int NTW  = DOUT / 16;        // n-tiles per warp
    constexpr int ASTB = 272;              // row stride bytes (128 fp16 + 16B pad)
    constexpr int SM_A = 0;
    constexpr int SM_B = SM_A + 128 * ASTB;

    const __half* Wh = (LAYER == 1) ? g_W1h : (LAYER == 2) ? g_W2h : g_W3h;

    extern __shared__ char sm[];
    const uint32_t smb = smem_u32(sm);
    const int t    = threadIdx.x;
    const int lane = t & 31;
    const int wid  = t >> 5;
    const int row0 = blockIdx.x * 128;

    // ---- stage B (W^T fp16, pure copy) ----
    for (int g = t; g < DOUT * 16; g += 512) {
        int nn = g >> 4, kg = g & 15;
        *(uint4*)(sm + SM_B + nn * ASTB + kg * 16) =
            *(const uint4*)((const char*)Wh + (size_t)g * 16);
    }

    // ---- stage A (pure copy from fp16 X) ----
    const uint4* X4 = (const uint4*)g_X16;   // 16 uint4 per 128-wide row
    for (int g = t; g < 128 * 16; g += 512) {
        int r = g >> 4, kg = g & 15;
        int row = row0 + r;
        uint4 v = make_uint4(0u, 0u, 0u, 0u);
        if (row < n) v = X4[(size_t)row * 16 + kg];
        *(uint4*)(sm + SM_A + r * ASTB + kg * 16) = v;
    }
    __syncthreads();

    // ---- compute ----
    const int m0 = (wid >> 1) * 16;
    const int ch = wid & 1;
    const int qd = lane >> 3;
    const int ri = lane & 7;

    float acc[NTW][4];
#pragma unroll
    for (int nt = 0; nt < NTW; nt++) { acc[nt][0] = acc[nt][1] = acc[nt][2] = acc[nt][3] = 0.f; }

    uint32_t aAddr = smb + SM_A + (uint32_t)(m0 + ri + ((qd & 1) << 3)) * ASTB
                   + (uint32_t)((qd & 2) ? 16 : 0);
    uint32_t bBase = smb + SM_B + (uint32_t)(ri + ((qd & 1) << 3)) * ASTB
                   + (uint32_t)((qd & 2) ? 16 : 0);
#pragma unroll
    for (int kk = 0; kk < 8; kk++) {
        uint32_t a0, a1, a2, a3;
        LDSM_X4(a0, a1, a2, a3, aAddr + kk * 32);
#pragma unroll
        for (int p = 0; p < NTW / 2; p++) {
            uint32_t bAddr = bBase + (uint32_t)((ch * NTW + 2 * p) * 8) * ASTB + kk * 32;
            uint32_t b0, b1, b2, b3;
            LDSM_X4(b0, b1, b2, b3, bAddr);
            MMA_F16(acc[2 * p],     a0, a1, a2, a3, b0, b2);
            MMA_F16(acc[2 * p + 1], a0, a1, a2, a3, b1, b3);
        }
    }

    // ---- epilogue: fp16 message writes ----
    const int frow = row0 + m0 + (lane >> 2);
    const int fcol = (lane & 3) * 2;
    uint32_t* H32 = (uint32_t*)g_H16;
#pragma unroll
    for (int nt = 0; nt < NTW; nt++) {
        int col = (ch * NTW + nt) * 8 + fcol;
        if (frow < n) {
            __half2 h = __floats2half2_rn(acc[nt][0], acc[nt][1]);
            H32[((size_t)frow * DOUT + col) >> 1] = *(uint32_t*)&h;
        }
        if (frow + 8 < n) {
            __half2 h = __floats2half2_rn(acc[nt][2], acc[nt][3]);
            H32[((size_t)(frow + 8) * DOUT + col) >> 1] = *(uint32_t*)&h;
        }
    }
}

// ---------------- fused aggregation + next-layer epilogue ----------------
// Gathers fp16 messages, fp32 accumulate (self-loop init), then
// X_next = relu(acc*in_norm + b)*out_norm written as fp16.
__global__ void __launch_bounds__(256)
k_agg128_fuse(const float* __restrict__ bprev, int n) {
    int w    = (blockIdx.x * blockDim.x + threadIdx.x) >> 5;
    int lane = threadIdx.x & 31;
    if (w >= n) return;
    const uint2* H2 = (const uint2*)g_H16;    // row = 32 uint2 (128 fp16)
    int beg = g_row_beg[w];
    int end = beg + g_ideg[w] - 1;
    float4 acc = make_float4(0.f, 0.f, 0.f, 0.f);
    acc_h4(acc, H2[(size_t)w * 32 + lane]);   // self-loop
    int j = beg;
    for (; j + 1 < end; j += 2) {
        int s0 = __ldg(&g_csr_src[j]);
        int s1 = __ldg(&g_csr_src[j + 1]);
        uint2 u0 = H2[(size_t)s0 * 32 + lane];
        uint2 u1 = H2[(size_t)s1 * 32 + lane];
        acc_h4(acc, u0);
        acc_h4(acc, u1);
    }
    if (j < end) {
        acc_h4(acc, H2[(size_t)__ldg(&g_csr_src[j]) * 32 + lane]);
    }
    float inn = g_in_norm[w];
    float on  = g_out_norm[w];
    float4 bb = ((const float4*)bprev)[lane];
    float x0 = fmaxf(fmaf(acc.x, inn, bb.x), 0.f) * on;
    float x1 = fmaxf(fmaf(acc.y, inn, bb.y), 0.f) * on;
    float x2 = fmaxf(fmaf(acc.z, inn, bb.z), 0.f) * on;
    float x3 = fmaxf(fmaf(acc.w, inn, bb.w), 0.f) * on;
    __half2 h0 = __floats2half2_rn(x0, x1);
    __half2 h1 = __floats2half2_rn(x2, x3);
    ((uint2*)g_X16)[(size_t)w * 32 + lane] = make_uint2(*(uint32_t*)&h0, *(uint32_t*)&h1);
}

// 64-wide, final layer: half-warp per dst node; out = acc*in_norm + b3 (fp32).
__global__ void __launch_bounds__(256)
k_agg64_final(const float* __restrict__ b3, float* __restrict__ out, int n) {
    int gt   = blockIdx.x * blockDim.x + threadIdx.x;
    int lane = gt & 31;
    int w    = gt >> 5;
    int sub  = lane >> 4;
    int l16  = lane & 15;
    int node = w * 2 + sub;
    if (node >= n) return;
    const uint2* H2 = (const uint2*)g_H16;    // row = 16 uint2 (64 fp16)
    int beg = g_row_beg[node];
    int end = beg + g_ideg[node] - 1;
    float4 acc = make_float4(0.f, 0.f, 0.f, 0.f);
    acc_h4(acc, H2[(size_t)node * 16 + l16]); // self-loop
    int j = beg;
    for (; j + 1 < end; j += 2) {
        int s0 = __ldg(&g_csr_src[j]);
        int s1 = __ldg(&g_csr_src[j + 1]);
        uint2 u0 = H2[(size_t)s0 * 16 + l16];
        uint2 u1 = H2[(size_t)s1 * 16 + l16];
        acc_h4(acc, u0);
        acc_h4(acc, u1);
    }
    if (j < end) {
        acc_h4(acc, H2[(size_t)__ldg(&g_csr_src[j]) * 16 + l16]);
    }
    float inn = g_in_norm[node];
    float4 bb = ((const float4*)b3)[l16];
    float4 o;
    o.x = fmaf(acc.x, inn, bb.x);
    o.y = fmaf(acc.y, inn, bb.y);
    o.z = fmaf(acc.z, inn, bb.z);
    o.w = fmaf(acc.w, inn, bb.w);
    ((float4*)out)[(size_t)node * 16 + l16] = o;
}

// ---------------- launcher ----------------
extern "C" void kernel_launch(void* const* d_in, const int* in_sizes, int n_in,
                              void* d_out, int out_size)
{
    const float* feat = (const float*)d_in[0];
    const int*   src  = (const int*)d_in[1];
    const int*   dst  = (const int*)d_in[2];
    const float* W1   = (const float*)d_in[3];
    const float* b1   = (const float*)d_in[4];
    const float* W2   = (const float*)d_in[5];
    const float* b2   = (const float*)d_in[6];
    const float* W3   = (const float*)d_in[7];
    const float* b3   = (const float*)d_in[8];
    float*       out  = (float*)d_out;

    const int n = in_sizes[0] / 128;   // 100000
    const int E = in_sizes[1];         // 1600000

    const int smem128 = (128 + 128) * 272;   // 69,632 B  -> 2 CTAs/SM
    const int smem64  = (128 + 64) * 272;    // 52,224 B
    cudaFuncSetAttribute((const void*)k_gemm_mma<128, 1>,
                         cudaFuncAttributeMaxDynamicSharedMemorySize, smem128);
    cudaFuncSetAttribute((const void*)k_gemm_mma<128, 2>,
                         cudaFuncAttributeMaxDynamicSharedMemorySize, smem128);
    cudaFuncSetAttribute((const void*)k_gemm_mma<64, 3>,
                         cudaFuncAttributeMaxDynamicSharedMemorySize, smem64);

    // W prep for all layers (once, up front)
    k_prepW_all<<<(40960 + 255) / 256, 256>>>(W1, W2, W3);

    // degrees
    k_init_deg<<<(n + 255) / 256, 256>>>(n);
    k_count_deg<<<1024, 256>>>(src, dst, E);

    // CSR build + norms (fused)
    k_alloc<<<(n + 255) / 256, 256>>>(n);
    k_scatter<<<1024, 256>>>(src, dst, E);

    // layer-1 input prep (feat * out_norm -> fp16)
    k_prepX1<<<(n * 32 + 255) / 256, 256>>>(feat, n);

    const int gblocks = (n + 127) / 128;   // 782

    // layer 1
    k_gemm_mma<128, 1><<<gblocks, 512, smem128>>>(n);
    k_agg128_fuse<<<(n * 32 + 255) / 256, 256>>>(b1, n);

    // layer 2
    k_gemm_mma<128, 2><<<gblocks, 512, smem128>>>(n);
    k_agg128_fuse<<<(n * 32 + 255) / 256, 256>>>(b2, n);

    // layer 3 (64-wide)
    k_gemm_mma<64, 3><<<gblocks, 512, smem64>>>(n);
    k_agg64_final<<<(n * 16 + 255) / 256, 256>>>(b3, out, n);
}

// round 15
// speedup vs baseline: 1.5676x; 1.0591x over previous
#include <cuda_runtime.h>
#include <cuda_fp16.h>
#include <cstdint>

#define NODES_MAX 100000
#define E_MAX     1600000

// ---------------- device scratch (static, allocation-free) ----------------
__device__ __half g_H16[(size_t)NODES_MAX * 128];   // messages (fp16)
__device__ __half g_X16[(size_t)NODES_MAX * 128];   // X_eff (fp16)
__device__ float  g_out_norm[NODES_MAX];
__device__ float  g_in_norm[NODES_MAX];
__device__ int    g_odeg[NODES_MAX];
__device__ int    g_ideg[NODES_MAX];
__device__ int    g_row_beg[NODES_MAX];
__device__ int    g_fill[NODES_MAX];
__device__ int    g_csr_src[E_MAX];
__device__ int    g_alloc_ctr;
__device__ __half g_W1h[128 * 128];                 // W^T fp16 [n][k]
__device__ __half g_W2h[128 * 128];
__device__ __half g_W3h[64 * 128];

__device__ __forceinline__ uint32_t smem_u32(const void* p) {
    uint32_t a;
    asm("{ .reg .u64 t; cvta.to.shared.u64 t, %1; cvt.u32.u64 %0, t; }" : "=r"(a) : "l"(p));
    return a;
}

#define LDSM_X4(r0, r1, r2, r3, addr) \
    asm volatile("ldmatrix.sync.aligned.m8n8.x4.shared.b16 {%0,%1,%2,%3}, [%4];" \
        : "=r"(r0), "=r"(r1), "=r"(r2), "=r"(r3) : "r"(addr))

#define MMA_F16(c, a0, a1, a2, a3, b0, b1) \
    asm volatile("mma.sync.aligned.m16n8k16.row.col.f32.f16.f16.f32 " \
        "{%0,%1,%2,%3}, {%4,%5,%6,%7}, {%8,%9}, {%0,%1,%2,%3};" \
        : "+f"((c)[0]), "+f"((c)[1]), "+f"((c)[2]), "+f"((c)[3]) \
        : "r"(a0), "r"(a1), "r"(a2), "r"(a3), "r"(b0), "r"(b1))

// unpack uint2 (4 fp16) and accumulate into float4
__device__ __forceinline__ void acc_h4(float4& acc, uint2 u) {
    __half2 h0 = *(__half2*)&u.x;
    __half2 h1 = *(__half2*)&u.y;
    float2 f0 = __half22float2(h0);
    float2 f1 = __half22float2(h1);
    acc.x += f0.x; acc.y += f0.y; acc.z += f1.x; acc.w += f1.y;
}

// ---------------- degree ----------------
__global__ void k_init_deg(int n) {
    int i = blockIdx.x * blockDim.x + threadIdx.x;
    if (i < n) { g_odeg[i] = 1; g_ideg[i] = 1; }
    if (i == 0) g_alloc_ctr = 0;
}
__global__ void k_count_deg(const int* __restrict__ src, const int* __restrict__ dst, int E) {
    int i = blockIdx.x * blockDim.x + threadIdx.x;
    int st = gridDim.x * blockDim.x;
    for (; i < E; i += st) {
        atomicAdd(&g_odeg[src[i]], 1);
        atomicAdd(&g_ideg[dst[i]], 1);
    }
}

// ---------------- CSR segment allocation + norms (fused) ----------------
__global__ void __launch_bounds__(256)
k_alloc(int n) {
    __shared__ int warp_sums[8];
    __shared__ int block_base;
    int i    = blockIdx.x * 256 + threadIdx.x;
    int lane = threadIdx.x & 31;
    int wid  = threadIdx.x >> 5;
    int ideg = (i < n) ? g_ideg[i] : 1;
    int deg  = ideg - 1;
    if (i < n) {
        g_out_norm[i] = rsqrtf((float)g_odeg[i]);
        g_in_norm[i]  = rsqrtf((float)ideg);
    }
    int v = deg;
#pragma unroll
    for (int off = 1; off < 32; off <<= 1) {
        int t = __shfl_up_sync(0xffffffffu, v, off);
        if (lane >= off) v += t;
    }
    if (lane == 31) warp_sums[wid] = v;
    __syncthreads();
    if (wid == 0) {
        int s = (lane < 8) ? warp_sums[lane] : 0;
#pragma unroll
        for (int off = 1; off < 8; off <<= 1) {
            int t = __shfl_up_sync(0xffffffffu, s, off);
            if (lane >= off) s += t;
        }
        if (lane < 8) warp_sums[lane] = s;
        if (lane == 7) block_base = atomicAdd(&g_alloc_ctr, s);
    }
    __syncthreads();
    int base = block_base + ((wid > 0) ? warp_sums[wid - 1] : 0) + (v - deg);
    if (i < n) { g_row_beg[i] = base; g_fill[i] = base; }
}

__global__ void k_scatter(const int* __restrict__ src, const int* __restrict__ dst, int E) {
    int i = blockIdx.x * blockDim.x + threadIdx.x;
    int st = gridDim.x * blockDim.x;
    for (; i < E; i += st) {
        int d = dst[i];
        int pos = atomicAdd(&g_fill[d], 1);
        g_csr_src[pos] = src[i];
    }
}

// ---------------- W prep: transpose to fp16, all 3 layers ----------------
__global__ void k_prepW_all(const float* __restrict__ W1, const float* __restrict__ W2,
                            const float* __restrict__ W3) {
    int i = blockIdx.x * blockDim.x + threadIdx.x;   // 0 .. 40959
    const float* W; __half* Wh; int dout, idx;
    if (i < 16384)      { W = W1; Wh = g_W1h; dout = 128; idx = i; }
    else if (i < 32768) { W = W2; Wh = g_W2h; dout = 128; idx = i - 16384; }
    else if (i < 40960) { W = W3; Wh = g_W3h; dout = 64;  idx = i - 32768; }
    else return;
    int nn = idx % dout;
    int k  = idx / dout;
    Wh[nn * 128 + k] = __float2half_rn(W[k * dout + nn]);
}

// ---------------- fp16 HMMA GEMM (single term, fp32 accum) ----------------
// 128-row tiles, 512 threads (16 warps: 8 row-groups x 2 col-halves).
// MODE 0: stage A from fp32 feat * out_norm (layer 1, fused prep)
// MODE 1: stage A as pure copy from fp16 g_X16
template <int DOUT, int MODE, int LAYER>
__global__ void __launch_bounds__(512, 2)
k_gemm_mma(const float* __restrict__ X0, int n)
{
    constexpr int NTW  = DOUT / 16;        // n-tiles per warp
    constexpr int ASTB = 272;              // row stride bytes (128 fp16 + 16B pad)
    constexpr int SM_A = 0;
    constexpr int SM_B = SM_A + 128 * ASTB;

    const __half* Wh = (LAYER == 1) ? g_W1h : (LAYER == 2) ? g_W2h : g_W3h;

    extern __shared__ char sm[];
    const uint32_t smb = smem_u32(sm);
    const int t    = threadIdx.x;
    const int lane = t & 31;
    const int wid  = t >> 5;
    const int row0 = blockIdx.x * 128;

    // ---- stage B (W^T fp16, pure copy) ----
    for (int g = t; g < DOUT * 16; g += 512) {
        int nn = g >> 4, kg = g & 15;
        *(uint4*)(sm + SM_B + nn * ASTB + kg * 16) =
            *(const uint4*)((const char*)Wh + (size_t)g * 16);
    }

    // ---- stage A ----
    for (int g = t; g < 128 * 16; g += 512) {
        int r = g >> 4, kg = g & 15;
        int row = row0 + r;
        uint4 v = make_uint4(0u, 0u, 0u, 0u);
        if (row < n) {
            if (MODE == 0) {
                float on = g_out_norm[row];
                float4 a = ((const float4*)X0)[(size_t)row * 32 + kg * 2];
                float4 b = ((const float4*)X0)[(size_t)row * 32 + kg * 2 + 1];
                __half2 h0 = __floats2half2_rn(a.x * on, a.y * on);
                __half2 h1 = __floats2half2_rn(a.z * on, a.w * on);
                __half2 h2 = __floats2half2_rn(b.x * on, b.y * on);
                __half2 h3 = __floats2half2_rn(b.z * on, b.w * on);
                v = make_uint4(*(uint32_t*)&h0, *(uint32_t*)&h1,
                               *(uint32_t*)&h2, *(uint32_t*)&h3);
            } else {
                v = ((const uint4*)g_X16)[(size_t)row * 16 + kg];
            }
        }
        *(uint4*)(sm + SM_A + r * ASTB + kg * 16) = v;
    }
    __syncthreads();

    // ---- compute ----
    const int m0 = (wid >> 1) * 16;
    const int ch = wid & 1;
    const int qd = lane >> 3;
    const int ri = lane & 7;

    float acc[NTW][4];
#pragma unroll
    for (int nt = 0; nt < NTW; nt++) { acc[nt][0] = acc[nt][1] = acc[nt][2] = acc[nt][3] = 0.f; }

    uint32_t aAddr = smb + SM_A + (uint32_t)(m0 + ri + ((qd & 1) << 3)) * ASTB
                   + (uint32_t)((qd & 2) ? 16 : 0);
    uint32_t bBase = smb + SM_B + (uint32_t)(ri + ((qd & 1) << 3)) * ASTB
                   + (uint32_t)((qd & 2) ? 16 : 0);
#pragma unroll
    for (int kk = 0; kk < 8; kk++) {
        uint32_t a0, a1, a2, a3;
        LDSM_X4(a0, a1, a2, a3, aAddr + kk * 32);
#pragma unroll
        for (int p = 0; p < NTW / 2; p++) {
            uint32_t bAddr = bBase + (uint32_t)((ch * NTW + 2 * p) * 8) * ASTB + kk * 32;
            uint32_t b0, b1, b2, b3;
            LDSM_X4(b0, b1, b2, b3, bAddr);
            MMA_F16(acc[2 * p],     a0, a1, a2, a3, b0, b2);
            MMA_F16(acc[2 * p + 1], a0, a1, a2, a3, b1, b3);
        }
    }

    // ---- epilogue: fp16 message writes ----
    const int frow = row0 + m0 + (lane >> 2);
    const int fcol = (lane & 3) * 2;
    uint32_t* H32 = (uint32_t*)g_H16;
#pragma unroll
    for (int nt = 0; nt < NTW; nt++) {
        int col = (ch * NTW + nt) * 8 + fcol;
        if (frow < n) {
            __half2 h = __floats2half2_rn(acc[nt][0], acc[nt][1]);
            H32[((size_t)frow * DOUT + col) >> 1] = *(uint32_t*)&h;
        }
        if (frow + 8 < n) {
            __half2 h = __floats2half2_rn(acc[nt][2], acc[nt][3]);
            H32[((size_t)(frow + 8) * DOUT + col) >> 1] = *(uint32_t*)&h;
        }
    }
}

// ---------------- fused aggregation + next-layer epilogue (unroll-4) ----------------
__global__ void __launch_bounds__(256)
k_agg128_fuse(const float* __restrict__ bprev, int n) {
    int w    = (blockIdx.x * blockDim.x + threadIdx.x) >> 5;
    int lane = threadIdx.x & 31;
    if (w >= n) return;
    const uint2* H2 = (const uint2*)g_H16;    // row = 32 uint2 (128 fp16)
    int beg = g_row_beg[w];
    int end = beg + g_ideg[w] - 1;
    float4 acc = make_float4(0.f, 0.f, 0.f, 0.f);
    acc_h4(acc, H2[(size_t)w * 32 + lane]);   // self-loop
    int j = beg;
    for (; j + 3 < end; j += 4) {
        int s0 = __ldg(&g_csr_src[j]);
        int s1 = __ldg(&g_csr_src[j + 1]);
        int s2 = __ldg(&g_csr_src[j + 2]);
        int s3 = __ldg(&g_csr_src[j + 3]);
        uint2 u0 = H2[(size_t)s0 * 32 + lane];
        uint2 u1 = H2[(size_t)s1 * 32 + lane];
        uint2 u2 = H2[(size_t)s2 * 32 + lane];
        uint2 u3 = H2[(size_t)s3 * 32 + lane];
        acc_h4(acc, u0); acc_h4(acc, u1); acc_h4(acc, u2); acc_h4(acc, u3);
    }
    for (; j < end; j++) {
        acc_h4(acc, H2[(size_t)__ldg(&g_csr_src[j]) * 32 + lane]);
    }
    float inn = g_in_norm[w];
    float on  = g_out_norm[w];
    float4 bb = ((const float4*)bprev)[lane];
    float x0 = fmaxf(fmaf(acc.x, inn, bb.x), 0.f) * on;
    float x1 = fmaxf(fmaf(acc.y, inn, bb.y), 0.f) * on;
    float x2 = fmaxf(fmaf(acc.z, inn, bb.z), 0.f) * on;
    float x3 = fmaxf(fmaf(acc.w, inn, bb.w), 0.f) * on;
    __half2 h0 = __floats2half2_rn(x0, x1);
    __half2 h1 = __floats2half2_rn(x2, x3);
    ((uint2*)g_X16)[(size_t)w * 32 + lane] = make_uint2(*(uint32_t*)&h0, *(uint32_t*)&h1);
}

// 64-wide, final layer: half-warp per dst node; out = acc*in_norm + b3 (fp32).
__global__ void __launch_bounds__(256)
k_agg64_final(const float* __restrict__ b3, float* __restrict__ out, int n) {
    int gt   = blockIdx.x * blockDim.x + threadIdx.x;
    int lane = gt & 31;
    int w    = gt >> 5;
    int sub  = lane >> 4;
    int l16  = lane & 15;
    int node = w * 2 + sub;
    if (node >= n) return;
    const uint2* H2 = (const uint2*)g_H16;    // row = 16 uint2 (64 fp16)
    int beg = g_row_beg[node];
    int end = beg + g_ideg[node] - 1;
    float4 acc = make_float4(0.f, 0.f, 0.f, 0.f);
    acc_h4(acc, H2[(size_t)node * 16 + l16]); // self-loop
    int j = beg;
    for (; j + 3 < end; j += 4) {
        int s0 = __ldg(&g_csr_src[j]);
        int s1 = __ldg(&g_csr_src[j + 1]);
        int s2 = __ldg(&g_csr_src[j + 2]);
        int s3 = __ldg(&g_csr_src[j + 3]);
        uint2 u0 = H2[(size_t)s0 * 16 + l16];
        uint2 u1 = H2[(size_t)s1 * 16 + l16];
        uint2 u2 = H2[(size_t)s2 * 16 + l16];
        uint2 u3 = H2[(size_t)s3 * 16 + l16];
        acc_h4(acc, u0); acc_h4(acc, u1); acc_h4(acc, u2); acc_h4(acc, u3);
    }
    for (; j < end; j++) {
        acc_h4(acc, H2[(size_t)__ldg(&g_csr_src[j]) * 16 + l16]);
    }
    float inn = g_in_norm[node];
    float4 bb = ((const float4*)b3)[l16];
    float4 o;
    o.x = fmaf(acc.x, inn, bb.x);
    o.y = fmaf(acc.y, inn, bb.y);
    o.z = fmaf(acc.z, inn, bb.z);
    o.w = fmaf(acc.w, inn, bb.w);
    ((float4*)out)[(size_t)node * 16 + l16] = o;
}

// ---------------- launcher ----------------
extern "C" void kernel_launch(void* const* d_in, const int* in_sizes, int n_in,
                              void* d_out, int out_size)
{
    const float* feat = (const float*)d_in[0];
    const int*   src  = (const int*)d_in[1];
    const int*   dst  = (const int*)d_in[2];
    const float* W1   = (const float*)d_in[3];
    const float* b1   = (const float*)d_in[4];
    const float* W2   = (const float*)d_in[5];
    const float* b2   = (const float*)d_in[6];
    const float* W3   = (const float*)d_in[7];
    const float* b3   = (const float*)d_in[8];
    float*       out  = (float*)d_out;

    const int n = in_sizes[0] / 128;   // 100000
    const int E = in_sizes[1];         // 1600000

    const int smem128 = (128 + 128) * 272;   // 69,632 B  -> 2 CTAs/SM
    const int smem64  = (128 + 64) * 272;    // 52,224 B
    cudaFuncSetAttribute((const void*)k_gemm_mma<128, 0, 1>,
                         cudaFuncAttributeMaxDynamicSharedMemorySize, smem128);
    cudaFuncSetAttribute((const void*)k_gemm_mma<128, 1, 2>,
                         cudaFuncAttributeMaxDynamicSharedMemorySize, smem128);
    cudaFuncSetAttribute((const void*)k_gemm_mma<64, 1, 3>,
                         cudaFuncAttributeMaxDynamicSharedMemorySize, smem64);

    // W prep for all layers (once, up front)
    k_prepW_all<<<(40960 + 255) / 256, 256>>>(W1, W2, W3);

    // degrees
    k_init_deg<<<(n + 255) / 256, 256>>>(n);
    k_count_deg<<<1024, 256>>>(src, dst, E);

    // CSR build + norms (fused)
    k_alloc<<<(n + 255) / 256, 256>>>(n);
    k_scatter<<<1024, 256>>>(src, dst, E);

    const int gblocks = (n + 127) / 128;   // 782

    // layer 1 (fused feat prep in staging)
    k_gemm_mma<128, 0, 1><<<gblocks, 512, smem128>>>(feat, n);
    k_agg128_fuse<<<(n * 32 + 255) / 256, 256>>>(b1, n);

    // layer 2
    k_gemm_mma<128, 1, 2><<<gblocks, 512, smem128>>>(nullptr, n);
    k_agg128_fuse<<<(n * 32 + 255) / 256, 256>>>(b2, n);

    // layer 3 (64-wide)
    k_gemm_mma<64, 1, 3><<<gblocks, 512, smem64>>>(nullptr, n);
    k_agg64_final<<<(n * 16 + 255) / 256, 256>>>(b3, out, n);
}

// round 16
// speedup vs baseline: 1.6208x; 1.0339x over previous
#include <cuda_runtime.h>
#include <cuda_fp16.h>
#include <cstdint>

#define NODES_MAX 100000
#define E_MAX     1600000

// ---------------- device scratch (static, allocation-free) ----------------
__device__ __half g_H16[(size_t)NODES_MAX * 128];   // messages (fp16)
__device__ __half g_X16[(size_t)NODES_MAX * 128];   // X_eff (fp16)
__device__ float  g_out_norm[NODES_MAX];
__device__ float  g_in_norm[NODES_MAX];
__device__ int    g_odeg[NODES_MAX];                // real out-edge count (no self-loop)
__device__ int    g_ideg[NODES_MAX];                // real in-edge count (no self-loop)
__device__ int    g_row_beg[NODES_MAX];
__device__ int    g_fill[NODES_MAX];
__device__ int    g_csr_src[E_MAX];
__device__ int    g_alloc_ctr;
__device__ __half g_W1h[128 * 128];                 // W^T fp16 [n][k]
__device__ __half g_W2h[128 * 128];
__device__ __half g_W3h[64 * 128];

__device__ __forceinline__ uint32_t smem_u32(const void* p) {
    uint32_t a;
    asm("{ .reg .u64 t; cvta.to.shared.u64 t, %1; cvt.u32.u64 %0, t; }" : "=r"(a) : "l"(p));
    return a;
}

#define LDSM_X4(r0, r1, r2, r3, addr) \
    asm volatile("ldmatrix.sync.aligned.m8n8.x4.shared.b16 {%0,%1,%2,%3}, [%4];" \
        : "=r"(r0), "=r"(r1), "=r"(r2), "=r"(r3) : "r"(addr))

#define MMA_F16(c, a0, a1, a2, a3, b0, b1) \
    asm volatile("mma.sync.aligned.m16n8k16.row.col.f32.f16.f16.f32 " \
        "{%0,%1,%2,%3}, {%4,%5,%6,%7}, {%8,%9}, {%0,%1,%2,%3};" \
        : "+f"((c)[0]), "+f"((c)[1]), "+f"((c)[2]), "+f"((c)[3]) \
        : "r"(a0), "r"(a1), "r"(a2), "r"(a3), "r"(b0), "r"(b1))

// unpack 4 fp16 (two b32 words) into float4 accumulator
__device__ __forceinline__ void acc_h4(float4& acc, uint32_t x, uint32_t y) {
    __half2 h0 = *(__half2*)&x;
    __half2 h1 = *(__half2*)&y;
    float2 f0 = __half22float2(h0);
    float2 f1 = __half22float2(h1);
    acc.x += f0.x; acc.y += f0.y; acc.z += f1.x; acc.w += f1.y;
}
// unpack uint4 (8 fp16) into two float4 accumulators
__device__ __forceinline__ void acc_h8(float4& a, float4& b, uint4 u) {
    acc_h4(a, u.x, u.y);
    acc_h4(b, u.z, u.w);
}

// ---------------- setup: degree init + W transpose/convert (merged) ----------------
__global__ void k_init_prep(const float* __restrict__ W1, const float* __restrict__ W2,
                            const float* __restrict__ W3, int n) {
    int i = blockIdx.x * blockDim.x + threadIdx.x;
    if (i < n) { g_odeg[i] = 0; g_ideg[i] = 0; }
    if (i == 0) g_alloc_ctr = 0;
    if (i < 40960) {
        const float* W; __half* Wh; int dout, idx;
        if (i < 16384)      { W = W1; Wh = g_W1h; dout = 128; idx = i; }
        else if (i < 32768) { W = W2; Wh = g_W2h; dout = 128; idx = i - 16384; }
        else                { W = W3; Wh = g_W3h; dout = 64;  idx = i - 32768; }
        int nn = idx % dout;
        int k  = idx / dout;
        Wh[nn * 128 + k] = __float2half_rn(W[k * dout + nn]);
    }
}

__global__ void k_count_deg(const int* __restrict__ src, const int* __restrict__ dst, int E) {
    int i = blockIdx.x * blockDim.x + threadIdx.x;
    int st = gridDim.x * blockDim.x;
    for (; i < E; i += st) {
        atomicAdd(&g_odeg[src[i]], 1);
        atomicAdd(&g_ideg[dst[i]], 1);
    }
}

// ---------------- CSR segment allocation + norms (fused) ----------------
__global__ void __launch_bounds__(256)
k_alloc(int n) {
    __shared__ int warp_sums[8];
    __shared__ int block_base;
    int i    = blockIdx.x * 256 + threadIdx.x;
    int lane = threadIdx.x & 31;
    int wid  = threadIdx.x >> 5;
    int deg  = (i < n) ? g_ideg[i] : 0;      // real in-edges = CSR segment size
    if (i < n) {
        g_out_norm[i] = rsqrtf((float)(g_odeg[i] + 1));   // +1 self-loop
        g_in_norm[i]  = rsqrtf((float)(deg + 1));
    }
    int v = deg;
#pragma unroll
    for (int off = 1; off < 32; off <<= 1) {
        int t = __shfl_up_sync(0xffffffffu, v, off);
        if (lane >= off) v += t;
    }
    if (lane == 31) warp_sums[wid] = v;
    __syncthreads();
    if (wid == 0) {
        int s = (lane < 8) ? warp_sums[lane] : 0;
#pragma unroll
        for (int off = 1; off < 8; off <<= 1) {
            int t = __shfl_up_sync(0xffffffffu, s, off);
            if (lane >= off) s += t;
        }
        if (lane < 8) warp_sums[lane] = s;
        if (lane == 7) block_base = atomicAdd(&g_alloc_ctr, s);
    }
    __syncthreads();
    int base = block_base + ((wid > 0) ? warp_sums[wid - 1] : 0) + (v - deg);
    if (i < n) { g_row_beg[i] = base; g_fill[i] = base; }
}

// ---------------- GEMM body (shared by standalone + merged kernels) ----------------
// 128-row tiles, 512 threads (16 warps: 8 row-groups x 2 col-halves).
// MODE 0: stage A from fp32 feat * out_norm; MODE 1: pure copy from fp16 g_X16.
template <int DOUT, int MODE, int LAYER>
__device__ __forceinline__ void gemm_body(const float* __restrict__ X0, int n,
                                          char* sm, int bid) {
    constexpr int NTW  = DOUT / 16;
    constexpr int ASTB = 272;
    constexpr int SM_A = 0;
    constexpr int SM_B = SM_A + 128 * ASTB;

    const __half* Wh = (LAYER == 1) ? g_W1h : (LAYER == 2) ? g_W2h : g_W3h;

    const uint32_t smb = smem_u32(sm);
    const int t    = threadIdx.x;
    const int lane = t & 31;
    const int wid  = t >> 5;
    const int row0 = bid * 128;

    // stage B
    for (int g = t; g < DOUT * 16; g += 512) {
        int nn = g >> 4, kg = g & 15;
        *(uint4*)(sm + SM_B + nn * ASTB + kg * 16) =
            *(const uint4*)((const char*)Wh + (size_t)g * 16);
    }
    // stage A
    for (int g = t; g < 128 * 16; g += 512) {
        int r = g >> 4, kg = g & 15;
        int row = row0 + r;
        uint4 v = make_uint4(0u, 0u, 0u, 0u);
        if (row < n) {
            if (MODE == 0) {
                float on = g_out_norm[row];
                float4 a = ((const float4*)X0)[(size_t)row * 32 + kg * 2];
                float4 b = ((const float4*)X0)[(size_t)row * 32 + kg * 2 + 1];
                __half2 h0 = __floats2half2_rn(a.x * on, a.y * on);
                __half2 h1 = __floats2half2_rn(a.z * on, a.w * on);
                __half2 h2 = __floats2half2_rn(b.x * on, b.y * on);
                __half2 h3 = __floats2half2_rn(b.z * on, b.w * on);
                v = make_uint4(*(uint32_t*)&h0, *(uint32_t*)&h1,
                               *(uint32_t*)&h2, *(uint32_t*)&h3);
            } else {
                v = ((const uint4*)g_X16)[(size_t)row * 16 + kg];
            }
        }
        *(uint4*)(sm + SM_A + r * ASTB + kg * 16) = v;
    }
    __syncthreads();

    const int m0 = (wid >> 1) * 16;
    const int ch = wid & 1;
    const int qd = lane >> 3;
    const int ri = lane & 7;

    float acc[NTW][4];
#pragma unroll
    for (int nt = 0; nt < NTW; nt++) { acc[nt][0] = acc[nt][1] = acc[nt][2] = acc[nt][3] = 0.f; }

    uint32_t aAddr = smb + SM_A + (uint32_t)(m0 + ri + ((qd & 1) << 3)) * ASTB
                   + (uint32_t)((qd & 2) ? 16 : 0);
    uint32_t bBase = smb + SM_B + (uint32_t)(ri + ((qd & 1) << 3)) * ASTB
                   + (uint32_t)((qd & 2) ? 16 : 0);
#pragma unroll
    for (int kk = 0; kk < 8; kk++) {
        uint32_t a0, a1, a2, a3;
        LDSM_X4(a0, a1, a2, a3, aAddr + kk * 32);
#pragma unroll
        for (int p = 0; p < NTW / 2; p++) {
            uint32_t bAddr = bBase + (uint32_t)((ch * NTW + 2 * p) * 8) * ASTB + kk * 32;
            uint32_t b0, b1, b2, b3;
            LDSM_X4(b0, b1, b2, b3, bAddr);
            MMA_F16(acc[2 * p],     a0, a1, a2, a3, b0, b2);
            MMA_F16(acc[2 * p + 1], a0, a1, a2, a3, b1, b3);
        }
    }

    const int frow = row0 + m0 + (lane >> 2);
    const int fcol = (lane & 3) * 2;
    uint32_t* H32 = (uint32_t*)g_H16;
#pragma unroll
    for (int nt = 0; nt < NTW; nt++) {
        int col = (ch * NTW + nt) * 8 + fcol;
        if (frow < n) {
            __half2 h = __floats2half2_rn(acc[nt][0], acc[nt][1]);
            H32[((size_t)frow * DOUT + col) >> 1] = *(uint32_t*)&h;
        }
        if (frow + 8 < n) {
            __half2 h = __floats2half2_rn(acc[nt][2], acc[nt][3]);
            H32[((size_t)(frow + 8) * DOUT + col) >> 1] = *(uint32_t*)&h;
        }
    }
}

template <int DOUT, int MODE, int LAYER>
__global__ void __launch_bounds__(512, 2)
k_gemm_mma(const float* __restrict__ X0, int n) {
    extern __shared__ char sm[];
    gemm_body<DOUT, MODE, LAYER>(X0, n, sm, blockIdx.x);
}

// ---------------- merged: CSR scatter (first sblocks) + layer-1 GEMM ----------------
__global__ void __launch_bounds__(512, 2)
k_gemm1_scatter(const float* __restrict__ feat, const int* __restrict__ src,
                const int* __restrict__ dst, int n, int E, int sblocks) {
    extern __shared__ char sm[];
    if ((int)blockIdx.x < sblocks) {
        int i  = blockIdx.x * 512 + threadIdx.x;
        int st = sblocks * 512;
        for (; i < E; i += st) {
            int d = dst[i];
            int pos = atomicAdd(&g_fill[d], 1);
            g_csr_src[pos] = src[i];
        }
    } else {
        gemm_body<128, 0, 1>(feat, n, sm, blockIdx.x - sblocks);
    }
}

// ---------------- fused aggregation + next-layer epilogue (uint4, 2 edges/iter) ------
__global__ void __launch_bounds__(256)
k_agg128_fuse(const float* __restrict__ bprev, int n) {
    int w    = (blockIdx.x * blockDim.x + threadIdx.x) >> 5;
    int lane = threadIdx.x & 31;
    if (w >= n) return;
    const int half = lane >> 4;    // which edge of the pair
    const int l16  = lane & 15;    // uint4 slot within row (16 x 16B = 256B)
    const uint4* H4 = (const uint4*)g_H16;
    int beg = g_row_beg[w];
    int end = beg + g_ideg[w];
    float4 aA = make_float4(0.f, 0.f, 0.f, 0.f);
    float4 aB = make_float4(0.f, 0.f, 0.f, 0.f);
    if (half == 0) acc_h8(aA, aB, H4[(size_t)w * 16 + l16]);   // self-loop
    int j = beg;
    for (; j + 3 < end; j += 4) {
        int s0 = __ldg(&g_csr_src[j + half]);
        int s1 = __ldg(&g_csr_src[j + 2 + half]);
        uint4 u0 = H4[(size_t)s0 * 16 + l16];
        uint4 u1 = H4[(size_t)s1 * 16 + l16];
        acc_h8(aA, aB, u0);
        acc_h8(aA, aB, u1);
    }
    for (; j + 1 < end; j += 2) {
        int s0 = __ldg(&g_csr_src[j + half]);
        acc_h8(aA, aB, H4[(size_t)s0 * 16 + l16]);
    }
    if (j < end && half == 0) {
        int s0 = __ldg(&g_csr_src[j]);
        acc_h8(aA, aB, H4[(size_t)s0 * 16 + l16]);
    }
    __syncwarp();
    // cross-half reduction: lane l + lane l^16 hold partials of the same columns
    aA.x += __shfl_xor_sync(0xffffffffu, aA.x, 16);
    aA.y += __shfl_xor_sync(0xffffffffu, aA.y, 16);
    aA.z += __shfl_xor_sync(0xffffffffu, aA.z, 16);
    aA.w += __shfl_xor_sync(0xffffffffu, aA.w, 16);
    aB.x += __shfl_xor_sync(0xffffffffu, aB.x, 16);
    aB.y += __shfl_xor_sync(0xffffffffu, aB.y, 16);
    aB.z += __shfl_xor_sync(0xffffffffu, aB.z, 16);
    aB.w += __shfl_xor_sync(0xffffffffu, aB.w, 16);
    if (half == 0) {
        float inn = g_in_norm[w];
        float on  = g_out_norm[w];
        float4 b0 = ((const float4*)bprev)[l16 * 2];
        float4 b1 = ((const float4*)bprev)[l16 * 2 + 1];
        float x0 = fmaxf(fmaf(aA.x, inn, b0.x), 0.f) * on;
        float x1 = fmaxf(fmaf(aA.y, inn, b0.y), 0.f) * on;
        float x2 = fmaxf(fmaf(aA.z, inn, b0.z), 0.f) * on;
        float x3 = fmaxf(fmaf(aA.w, inn, b0.w), 0.f) * on;
        float x4 = fmaxf(fmaf(aB.x, inn, b1.x), 0.f) * on;
        float x5 = fmaxf(fmaf(aB.y, inn, b1.y), 0.f) * on;
        float x6 = fmaxf(fmaf(aB.z, inn, b1.z), 0.f) * on;
        float x7 = fmaxf(fmaf(aB.w, inn, b1.w), 0.f) * on;
        __half2 h0 = __floats2half2_rn(x0, x1);
        __half2 h1 = __floats2half2_rn(x2, x3);
        __half2 h2 = __floats2half2_rn(x4, x5);
        __half2 h3 = __floats2half2_rn(x6, x7);
        ((uint4*)g_X16)[(size_t)w * 16 + l16] =
            make_uint4(*(uint32_t*)&h0, *(uint32_t*)&h1, *(uint32_t*)&h2, *(uint32_t*)&h3);
    }
}

// 64-wide, final layer: half-warp per dst node; out = acc*in_norm + b3 (fp32).
__global__ void __launch_bounds__(256)
k_agg64_final(const float* __restrict__ b3, float* __restrict__ out, int n) {
    int gt   = blockIdx.x * blockDim.x + threadIdx.x;
    int lane = gt & 31;
    int w    = gt >> 5;
    int sub  = lane >> 4;
    int l16  = lane & 15;
    int node = w * 2 + sub;
    if (node >= n) return;
    const uint2* H2 = (const uint2*)g_H16;    // row = 16 uint2 (64 fp16)
    int beg = g_row_beg[node];
    int end = beg + g_ideg[node];
    float4 acc = make_float4(0.f, 0.f, 0.f, 0.f);
    {
        uint2 u = H2[(size_t)node * 16 + l16];
        acc_h4(acc, u.x, u.y);                 // self-loop
    }
    int j = beg;
    for (; j + 3 < end; j += 4) {
        int s0 = __ldg(&g_csr_src[j]);
        int s1 = __ldg(&g_csr_src[j + 1]);
        int s2 = __ldg(&g_csr_src[j + 2]);
        int s3 = __ldg(&g_csr_src[j + 3]);
        uint2 u0 = H2[(size_t)s0 * 16 + l16];
        uint2 u1 = H2[(size_t)s1 * 16 + l16];
        uint2 u2 = H2[(size_t)s2 * 16 + l16];
        uint2 u3 = H2[(size_t)s3 * 16 + l16];
        acc_h4(acc, u0.x, u0.y); acc_h4(acc, u1.x, u1.y);
        acc_h4(acc, u2.x, u2.y); acc_h4(acc, u3.x, u3.y);
    }
    for (; j < end; j++) {
        uint2 u = H2[(size_t)__ldg(&g_csr_src[j]) * 16 + l16];
        acc_h4(acc, u.x, u.y);
    }
    float inn = g_in_norm[node];
    float4 bb = ((const float4*)b3)[l16];
    float4 o;
    o.x = fmaf(acc.x, inn, bb.x);
    o.y = fmaf(acc.y, inn, bb.y);
    o.z = fmaf(acc.z, inn, bb.z);
    o.w = fmaf(acc.w, inn, bb.w);
    ((float4*)out)[(size_t)node * 16 + l16] = o;
}

// ---------------- launcher ----------------
extern "C" void kernel_launch(void* const* d_in, const int* in_sizes, int n_in,
                              void* d_out, int out_size)
{
    const float* feat = (const float*)d_in[0];
    const int*   src  = (const int*)d_in[1];
    const int*   dst  = (const int*)d_in[2];
    const float* W1   = (const float*)d_in[3];
    const float* b1   = (const float*)d_in[4];
    const float* W2   = (const float*)d_in[5];
    const float* b2   = (const float*)d_in[6];
    const float* W3   = (const float*)d_in[7];
    const float* b3   = (const float*)d_in[8];
    float*       out  = (float*)d_out;

    const int n = in_sizes[0] / 128;   // 100000
    const int E = in_sizes[1];         // 1600000

    const int smem128 = (128 + 128) * 272;   // 69,632 B  -> 2 CTAs/SM
    const int smem64  = (128 + 64) * 272;    // 52,224 B
    cudaFuncSetAttribute((const void*)k_gemm1_scatter,
                         cudaFuncAttributeMaxDynamicSharedMemorySize, smem128);
    cudaFuncSetAttribute((const void*)k_gemm_mma<128, 1, 2>,
                         cudaFuncAttributeMaxDynamicSharedMemorySize, smem128);
    cudaFuncSetAttribute((const void*)k_gemm_mma<64, 1, 3>,
                         cudaFuncAttributeMaxDynamicSharedMemorySize, smem64);

    // setup: degree zero-init + W transpose/convert (one launch)
    k_init_prep<<<(n + 255) / 256, 256>>>(W1, W2, W3, n);
    k_count_deg<<<1024, 256>>>(src, dst, E);
    k_alloc<<<(n + 255) / 256, 256>>>(n);

    const int gblocks = (n + 127) / 128;   // 782
    const int sblocks = 256;               // scatter blocks (run first in the grid)

    // layer 1 GEMM overlapped with CSR scatter (independent after k_alloc)
    k_gemm1_scatter<<<sblocks + gblocks, 512, smem128>>>(feat, src, dst, n, E, sblocks);
    k_agg128_fuse<<<(n * 32 + 255) / 256, 256>>>(b1, n);

    // layer 2
    k_gemm_mma<128, 1, 2><<<gblocks, 512, smem128>>>(nullptr, n);
    k_agg128_fuse<<<(n * 32 + 255) / 256, 256>>>(b2, n);

    // layer 3 (64-wide)
    k_gemm_mma<64, 1, 3><<<gblocks, 512, smem64>>>(nullptr, n);
    k_agg64_final<<<(n * 16 + 255) / 256, 256>>>(b3, out, n);
}

// round 17
// speedup vs baseline: 1.6210x; 1.0001x over previous
#include <cuda_runtime.h>
#include <cuda_fp16.h>
#include <cstdint>

#define NODES_MAX 100000
#define E_MAX     1600000

// ---------------- device scratch (static, allocation-free) ----------------
__device__ __half g_H16[(size_t)NODES_MAX * 128];   // messages (fp16)
__device__ __half g_X16[(size_t)NODES_MAX * 128];   // X_eff (fp16)
__device__ float  g_out_norm[NODES_MAX];
__device__ float  g_in_norm[NODES_MAX];
__device__ int    g_odeg[NODES_MAX];                // real out-edge count
__device__ int    g_ideg[NODES_MAX];                // real in-edge count
__device__ int    g_row_beg[NODES_MAX];
__device__ int    g_fill[NODES_MAX];
__device__ int    g_csr_src[E_MAX];
__device__ int    g_alloc_ctr;
__device__ __half g_W1h[128 * 128];                 // W^T fp16 [n][k]
__device__ __half g_W2h[128 * 128];
__device__ __half g_W3h[64 * 128];

__device__ __forceinline__ uint32_t smem_u32(const void* p) {
    uint32_t a;
    asm("{ .reg .u64 t; cvta.to.shared.u64 t, %1; cvt.u32.u64 %0, t; }" : "=r"(a) : "l"(p));
    return a;
}

#define LDSM_X4(r0, r1, r2, r3, addr) \
    asm volatile("ldmatrix.sync.aligned.m8n8.x4.shared.b16 {%0,%1,%2,%3}, [%4];" \
        : "=r"(r0), "=r"(r1), "=r"(r2), "=r"(r3) : "r"(addr))

#define MMA_F16(c, a0, a1, a2, a3, b0, b1) \
    asm volatile("mma.sync.aligned.m16n8k16.row.col.f32.f16.f16.f32 " \
        "{%0,%1,%2,%3}, {%4,%5,%6,%7}, {%8,%9}, {%0,%1,%2,%3};" \
        : "+f"((c)[0]), "+f"((c)[1]), "+f"((c)[2]), "+f"((c)[3]) \
        : "r"(a0), "r"(a1), "r"(a2), "r"(a3), "r"(b0), "r"(b1))

__device__ __forceinline__ void acc_h4(float4& acc, uint32_t x, uint32_t y) {
    __half2 h0 = *(__half2*)&x;
    __half2 h1 = *(__half2*)&y;
    float2 f0 = __half22float2(h0);
    float2 f1 = __half22float2(h1);
    acc.x += f0.x; acc.y += f0.y; acc.z += f1.x; acc.w += f1.y;
}
__device__ __forceinline__ void acc_h8(float4& a, float4& b, uint4 u) {
    acc_h4(a, u.x, u.y);
    acc_h4(b, u.z, u.w);
}

// ---------------- setup: degree init + W transpose/convert (merged) ----------------
__global__ void k_init_prep(const float* __restrict__ W1, const float* __restrict__ W2,
                            const float* __restrict__ W3, int n) {
    int i = blockIdx.x * blockDim.x + threadIdx.x;
    if (i < n) { g_odeg[i] = 0; g_ideg[i] = 0; }
    if (i == 0) g_alloc_ctr = 0;
    if (i < 40960) {
        const float* W; __half* Wh; int dout, idx;
        if (i < 16384)      { W = W1; Wh = g_W1h; dout = 128; idx = i; }
        else if (i < 32768) { W = W2; Wh = g_W2h; dout = 128; idx = i - 16384; }
        else                { W = W3; Wh = g_W3h; dout = 64;  idx = i - 32768; }
        int nn = idx % dout;
        int k  = idx / dout;
        Wh[nn * 128 + k] = __float2half_rn(W[k * dout + nn]);
    }
}

// int4-vectorized degree count (4 edges per LDG)
__global__ void k_count_deg(const int* __restrict__ src, const int* __restrict__ dst, int E) {
    int i  = blockIdx.x * blockDim.x + threadIdx.x;
    int st = gridDim.x * blockDim.x;
    int E4 = E >> 2;
    const int4* s4 = (const int4*)src;
    const int4* d4 = (const int4*)dst;
    for (int j = i; j < E4; j += st) {
        int4 s = __ldg(&s4[j]);
        int4 d = __ldg(&d4[j]);
        atomicAdd(&g_odeg[s.x], 1); atomicAdd(&g_odeg[s.y], 1);
        atomicAdd(&g_odeg[s.z], 1); atomicAdd(&g_odeg[s.w], 1);
        atomicAdd(&g_ideg[d.x], 1); atomicAdd(&g_ideg[d.y], 1);
        atomicAdd(&g_ideg[d.z], 1); atomicAdd(&g_ideg[d.w], 1);
    }
    int tail = E & 3;
    if (i < tail) {
        int e = E4 * 4 + i;
        atomicAdd(&g_odeg[src[e]], 1);
        atomicAdd(&g_ideg[dst[e]], 1);
    }
}

// ---------------- CSR segment allocation + norms (fused) ----------------
__global__ void __launch_bounds__(256)
k_alloc(int n) {
    __shared__ int warp_sums[8];
    __shared__ int block_base;
    int i    = blockIdx.x * 256 + threadIdx.x;
    int lane = threadIdx.x & 31;
    int wid  = threadIdx.x >> 5;
    int deg  = (i < n) ? g_ideg[i] : 0;
    if (i < n) {
        g_out_norm[i] = rsqrtf((float)(g_odeg[i] + 1));
        g_in_norm[i]  = rsqrtf((float)(deg + 1));
    }
    int v = deg;
#pragma unroll
    for (int off = 1; off < 32; off <<= 1) {
        int t = __shfl_up_sync(0xffffffffu, v, off);
        if (lane >= off) v += t;
    }
    if (lane == 31) warp_sums[wid] = v;
    __syncthreads();
    if (wid == 0) {
        int s = (lane < 8) ? warp_sums[lane] : 0;
#pragma unroll
        for (int off = 1; off < 8; off <<= 1) {
            int t = __shfl_up_sync(0xffffffffu, s, off);
            if (lane >= off) s += t;
        }
        if (lane < 8) warp_sums[lane] = s;
        if (lane == 7) block_base = atomicAdd(&g_alloc_ctr, s);
    }
    __syncthreads();
    int base = block_base + ((wid > 0) ? warp_sums[wid - 1] : 0) + (v - deg);
    if (i < n) { g_row_beg[i] = base; g_fill[i] = base; }
}

// ---------------- GEMM body ----------------
template <int DOUT, int MODE, int LAYER>
__device__ __forceinline__ void gemm_body(const float* __restrict__ X0, int n,
                                          char* sm, int bid) {
    constexpr int NTW  = DOUT / 16;
    constexpr int ASTB = 272;
    constexpr int SM_A = 0;
    constexpr int SM_B = SM_A + 128 * ASTB;

    const __half* Wh = (LAYER == 1) ? g_W1h : (LAYER == 2) ? g_W2h : g_W3h;

    const uint32_t smb = smem_u32(sm);
    const int t    = threadIdx.x;
    const int lane = t & 31;
    const int wid  = t >> 5;
    const int row0 = bid * 128;

    for (int g = t; g < DOUT * 16; g += 512) {
        int nn = g >> 4, kg = g & 15;
        *(uint4*)(sm + SM_B + nn * ASTB + kg * 16) =
            *(const uint4*)((const char*)Wh + (size_t)g * 16);
    }
    for (int g = t; g < 128 * 16; g += 512) {
        int r = g >> 4, kg = g & 15;
        int row = row0 + r;
        uint4 v = make_uint4(0u, 0u, 0u, 0u);
        if (row < n) {
            if (MODE == 0) {
                float on = g_out_norm[row];
                float4 a = ((const float4*)X0)[(size_t)row * 32 + kg * 2];
                float4 b = ((const float4*)X0)[(size_t)row * 32 + kg * 2 + 1];
                __half2 h0 = __floats2half2_rn(a.x * on, a.y * on);
                __half2 h1 = __floats2half2_rn(a.z * on, a.w * on);
                __half2 h2 = __floats2half2_rn(b.x * on, b.y * on);
                __half2 h3 = __floats2half2_rn(b.z * on, b.w * on);
                v = make_uint4(*(uint32_t*)&h0, *(uint32_t*)&h1,
                               *(uint32_t*)&h2, *(uint32_t*)&h3);
            } else {
                v = ((const uint4*)g_X16)[(size_t)row * 16 + kg];
            }
        }
        *(uint4*)(sm + SM_A + r * ASTB + kg * 16) = v;
    }
    __syncthreads();

    const int m0 = (wid >> 1) * 16;
    const int ch = wid & 1;
    const int qd = lane >> 3;
    const int ri = lane & 7;

    float acc[NTW][4];
#pragma unroll
    for (int nt = 0; nt < NTW; nt++) { acc[nt][0] = acc[nt][1] = acc[nt][2] = acc[nt][3] = 0.f; }

    uint32_t aAddr = smb + SM_A + (uint32_t)(m0 + ri + ((qd & 1) << 3)) * ASTB
                   + (uint32_t)((qd & 2) ? 16 : 0);
    uint32_t bBase = smb + SM_B + (uint32_t)(ri + ((qd & 1) << 3)) * ASTB
                   + (uint32_t)((qd & 2) ? 16 : 0);
#pragma unroll
    for (int kk = 0; kk < 8; kk++) {
        uint32_t a0, a1, a2, a3;
        LDSM_X4(a0, a1, a2, a3, aAddr + kk * 32);
#pragma unroll
        for (int p = 0; p < NTW / 2; p++) {
            uint32_t bAddr = bBase + (uint32_t)((ch * NTW + 2 * p) * 8) * ASTB + kk * 32;
            uint32_t b0, b1, b2, b3;
            LDSM_X4(b0, b1, b2, b3, bAddr);
            MMA_F16(acc[2 * p],     a0, a1, a2, a3, b0, b2);
            MMA_F16(acc[2 * p + 1], a0, a1, a2, a3, b1, b3);
        }
    }

    const int frow = row0 + m0 + (lane >> 2);
    const int fcol = (lane & 3) * 2;
    uint32_t* H32 = (uint32_t*)g_H16;
#pragma unroll
    for (int nt = 0; nt < NTW; nt++) {
        int col = (ch * NTW + nt) * 8 + fcol;
        if (frow < n) {
            __half2 h = __floats2half2_rn(acc[nt][0], acc[nt][1]);
            H32[((size_t)frow * DOUT + col) >> 1] = *(uint32_t*)&h;
        }
        if (frow + 8 < n) {
            __half2 h = __floats2half2_rn(acc[nt][2], acc[nt][3]);
            H32[((size_t)(frow + 8) * DOUT + col) >> 1] = *(uint32_t*)&h;
        }
    }
}

template <int DOUT, int MODE, int LAYER>
__global__ void __launch_bounds__(512, 2)
k_gemm_mma(const float* __restrict__ X0, int n) {
    extern __shared__ char sm[];
    gemm_body<DOUT, MODE, LAYER>(X0, n, sm, blockIdx.x);
}

// ---------------- merged: CSR scatter (int4 edges, first sblocks) + layer-1 GEMM ----
__global__ void __launch_bounds__(512, 2)
k_gemm1_scatter(const float* __restrict__ feat, const int* __restrict__ src,
                const int* __restrict__ dst, int n, int E, int sblocks) {
    extern __shared__ char sm[];
    if ((int)blockIdx.x < sblocks) {
        int i  = blockIdx.x * 512 + threadIdx.x;
        int st = sblocks * 512;
        int E4 = E >> 2;
        const int4* s4 = (const int4*)src;
        const int4* d4 = (const int4*)dst;
        for (int j = i; j < E4; j += st) {
            int4 s = __ldg(&s4[j]);
            int4 d = __ldg(&d4[j]);
            g_csr_src[atomicAdd(&g_fill[d.x], 1)] = s.x;
            g_csr_src[atomicAdd(&g_fill[d.y], 1)] = s.y;
            g_csr_src[atomicAdd(&g_fill[d.z], 1)] = s.z;
            g_csr_src[atomicAdd(&g_fill[d.w], 1)] = s.w;
        }
        int tail = E & 3;
        if (i < tail) {
            int e = E4 * 4 + i;
            g_csr_src[atomicAdd(&g_fill[dst[e]], 1)] = src[e];
        }
    } else {
        gemm_body<128, 0, 1>(feat, n, sm, blockIdx.x - sblocks);
    }
}

// ---------------- fused aggregation + next-layer epilogue (MLP-8) ----------------
__global__ void __launch_bounds__(256)
k_agg128_fuse(const float* __restrict__ bprev, int n) {
    int w    = (blockIdx.x * blockDim.x + threadIdx.x) >> 5;
    int lane = threadIdx.x & 31;
    if (w >= n) return;
    const int half = lane >> 4;
    const int l16  = lane & 15;
    const uint4* H4 = (const uint4*)g_H16;
    int beg = g_row_beg[w];
    int end = beg + g_ideg[w];
    float4 aA = make_float4(0.f, 0.f, 0.f, 0.f);
    float4 aB = make_float4(0.f, 0.f, 0.f, 0.f);
    if (half == 0) acc_h8(aA, aB, H4[(size_t)w * 16 + l16]);   // self-loop
    int j = beg;
    for (; j + 7 < end; j += 8) {
        int s0 = __ldg(&g_csr_src[j + half]);
        int s1 = __ldg(&g_csr_src[j + 2 + half]);
        int s2 = __ldg(&g_csr_src[j + 4 + half]);
        int s3 = __ldg(&g_csr_src[j + 6 + half]);
        uint4 u0 = H4[(size_t)s0 * 16 + l16];
        uint4 u1 = H4[(size_t)s1 * 16 + l16];
        uint4 u2 = H4[(size_t)s2 * 16 + l16];
        uint4 u3 = H4[(size_t)s3 * 16 + l16];
        acc_h8(aA, aB, u0); acc_h8(aA, aB, u1);
        acc_h8(aA, aB, u2); acc_h8(aA, aB, u3);
    }
    for (; j + 1 < end; j += 2) {
        int s0 = __ldg(&g_csr_src[j + half]);
        acc_h8(aA, aB, H4[(size_t)s0 * 16 + l16]);
    }
    if (j < end && half == 0) {
        int s0 = __ldg(&g_csr_src[j]);
        acc_h8(aA, aB, H4[(size_t)s0 * 16 + l16]);
    }
    __syncwarp();
    aA.x += __shfl_xor_sync(0xffffffffu, aA.x, 16);
    aA.y += __shfl_xor_sync(0xffffffffu, aA.y, 16);
    aA.z += __shfl_xor_sync(0xffffffffu, aA.z, 16);
    aA.w += __shfl_xor_sync(0xffffffffu, aA.w, 16);
    aB.x += __shfl_xor_sync(0xffffffffu, aB.x, 16);
    aB.y += __shfl_xor_sync(0xffffffffu, aB.y, 16);
    aB.z += __shfl_xor_sync(0xffffffffu, aB.z, 16);
    aB.w += __shfl_xor_sync(0xffffffffu, aB.w, 16);
    if (half == 0) {
        float inn = g_in_norm[w];
        float on  = g_out_norm[w];
        float4 b0 = ((const float4*)bprev)[l16 * 2];
        float4 b1 = ((const float4*)bprev)[l16 * 2 + 1];
        float x0 = fmaxf(fmaf(aA.x, inn, b0.x), 0.f) * on;
        float x1 = fmaxf(fmaf(aA.y, inn, b0.y), 0.f) * on;
        float x2 = fmaxf(fmaf(aA.z, inn, b0.z), 0.f) * on;
        float x3 = fmaxf(fmaf(aA.w, inn, b0.w), 0.f) * on;
        float x4 = fmaxf(fmaf(aB.x, inn, b1.x), 0.f) * on;
        float x5 = fmaxf(fmaf(aB.y, inn, b1.y), 0.f) * on;
        float x6 = fmaxf(fmaf(aB.z, inn, b1.z), 0.f) * on;
        float x7 = fmaxf(fmaf(aB.w, inn, b1.w), 0.f) * on;
        __half2 h0 = __floats2half2_rn(x0, x1);
        __half2 h1 = __floats2half2_rn(x2, x3);
        __half2 h2 = __floats2half2_rn(x4, x5);
        __half2 h3 = __floats2half2_rn(x6, x7);
        ((uint4*)g_X16)[(size_t)w * 16 + l16] =
            make_uint4(*(uint32_t*)&h0, *(uint32_t*)&h1, *(uint32_t*)&h2, *(uint32_t*)&h3);
    }
}

// 64-wide, final layer (MLP-8): half-warp per dst node; out = acc*in_norm + b3.
__global__ void __launch_bounds__(256)
k_agg64_final(const float* __restrict__ b3, float* __restrict__ out, int n) {
    int gt   = blockIdx.x * blockDim.x + threadIdx.x;
    int lane = gt & 31;
    int w    = gt >> 5;
    int sub  = lane >> 4;
    int l16  = lane & 15;
    int node = w * 2 + sub;
    if (node >= n) return;
    const uint2* H2 = (const uint2*)g_H16;
    int beg = g_row_beg[node];
    int end = beg + g_ideg[node];
    float4 acc = make_float4(0.f, 0.f, 0.f, 0.f);
    {
        uint2 u = H2[(size_t)node * 16 + l16];
        acc_h4(acc, u.x, u.y);
    }
    int j = beg;
    for (; j + 7 < end; j += 8) {
        int s0 = __ldg(&g_csr_src[j]);
        int s1 = __ldg(&g_csr_src[j + 1]);
        int s2 = __ldg(&g_csr_src[j + 2]);
        int s3 = __ldg(&g_csr_src[j + 3]);
        int s4 = __ldg(&g_csr_src[j + 4]);
        int s5 = __ldg(&g_csr_src[j + 5]);
        int s6 = __ldg(&g_csr_src[j + 6]);
        int s7 = __ldg(&g_csr_src[j + 7]);
        uint2 u0 = H2[(size_t)s0 * 16 + l16];
        uint2 u1 = H2[(size_t)s1 * 16 + l16];
        uint2 u2 = H2[(size_t)s2 * 16 + l16];
        uint2 u3 = H2[(size_t)s3 * 16 + l16];
        uint2 u4 = H2[(size_t)s4 * 16 + l16];
        uint2 u5 = H2[(size_t)s5 * 16 + l16];
        uint2 u6 = H2[(size_t)s6 * 16 + l16];
        uint2 u7 = H2[(size_t)s7 * 16 + l16];
        acc_h4(acc, u0.x, u0.y); acc_h4(acc, u1.x, u1.y);
        acc_h4(acc, u2.x, u2.y); acc_h4(acc, u3.x, u3.y);
        acc_h4(acc, u4.x, u4.y); acc_h4(acc, u5.x, u5.y);
        acc_h4(acc, u6.x, u6.y); acc_h4(acc, u7.x, u7.y);
    }
    for (; j < end; j++) {
        uint2 u = H2[(size_t)__ldg(&g_csr_src[j]) * 16 + l16];
        acc_h4(acc, u.x, u.y);
    }
    float inn = g_in_norm[node];
    float4 bb = ((const float4*)b3)[l16];
    float4 o;
    o.x = fmaf(acc.x, inn, bb.x);
    o.y = fmaf(acc.y, inn, bb.y);
    o.z = fmaf(acc.z, inn, bb.z);
    o.w = fmaf(acc.w, inn, bb.w);
    ((float4*)out)[(size_t)node * 16 + l16] = o;
}

// ---------------- launcher ----------------
extern "C" void kernel_launch(void* const* d_in, const int* in_sizes, int n_in,
                              void* d_out, int out_size)
{
    const float* feat = (const float*)d_in[0];
    const int*   src  = (const int*)d_in[1];
    const int*   dst  = (const int*)d_in[2];
    const float* W1   = (const float*)d_in[3];
    const float* b1   = (const float*)d_in[4];
    const float* W2   = (const float*)d_in[5];
    const float* b2   = (const float*)d_in[6];
    const float* W3   = (const float*)d_in[7];
    const float* b3   = (const float*)d_in[8];
    float*       out  = (float*)d_out;

    const int n = in_sizes[0] / 128;   // 100000
    const int E = in_sizes[1];         // 1600000

    const int smem128 = (128 + 128) * 272;   // 69,632 B  -> 2 CTAs/SM
    const int smem64  = (128 + 64) * 272;    // 52,224 B
    cudaFuncSetAttribute((const void*)k_gemm1_scatter,
                         cudaFuncAttributeMaxDynamicSharedMemorySize, smem128);
    cudaFuncSetAttribute((const void*)k_gemm_mma<128, 1, 2>,
                         cudaFuncAttributeMaxDynamicSharedMemorySize, smem128);
    cudaFuncSetAttribute((const void*)k_gemm_mma<64, 1, 3>,
                         cudaFuncAttributeMaxDynamicSharedMemorySize, smem64);

    // setup
    k_init_prep<<<(n + 255) / 256, 256>>>(W1, W2, W3, n);
    k_count_deg<<<1024, 256>>>(src, dst, E);
    k_alloc<<<(n + 255) / 256, 256>>>(n);

    const int gblocks = (n + 127) / 128;   // 782
    const int sblocks = 256;

    // layer 1 GEMM overlapped with CSR scatter
    k_gemm1_scatter<<<sblocks + gblocks, 512, smem128>>>(feat, src, dst, n, E, sblocks);
    k_agg128_fuse<<<(n * 32 + 255) / 256, 256>>>(b1, n);

    // layer 2
    k_gemm_mma<128, 1, 2><<<gblocks, 512, smem128>>>(nullptr, n);
    k_agg128_fuse<<<(n * 32 + 255) / 256, 256>>>(b2, n);

    // layer 3 (64-wide)
    k_gemm_mma<64, 1, 3><<<gblocks, 512, smem64>>>(nullptr, n);
    k_agg64_final<<<(n * 16 + 255) / 256, 256>>>(b3, out, n);
}